// round 6
// baseline (speedup 1.0000x reference)
#include <cuda_runtime.h>
#include <stdint.h>

#define ROWLEN 8192
#define NT     1024
#define NPT    8              // ROWLEN / NT
#define NWARP  32
#define KSEL   128
#define NBIN   1024

// Per-row top-K of relu(x): keep the K largest positive values, zero the rest.
// Selection = iterative 1024-way histogram refinement over positive-float bit
// space (bits of positive floats are order-isomorphic to uint32). Ties at the
// threshold are broken by LOWEST COLUMN INDEX, matching jax.lax.top_k, via a
// deterministic block scan (no atomics -> identical output on every call).
__global__ __launch_bounds__(NT, 2)
void topk_relu_kernel(const float* __restrict__ x, float* __restrict__ out) {
    __shared__ uint32_t s_hist[NBIN];
    __shared__ uint32_t s_w[NWARP];
    __shared__ uint32_t s_bc[4];   // [0]=bstar/total [1]=above_new [2]=h [3]=found

    const int tid  = threadIdx.x;
    const int wid  = tid >> 5;
    const int lane = tid & 31;
    const size_t base = (size_t)blockIdx.x * ROWLEN;

    s_hist[tid] = 0u;

    // ---- single HBM read: row -> registers ----
    // v[4*i+e] holds column 4*(i*NT + tid) + e  => column order = (i, tid, e)
    float v[NPT];
    {
        const float4* __restrict__ xv = reinterpret_cast<const float4*>(x + base);
#pragma unroll
        for (int i = 0; i < 2; i++) {
            float4 f = xv[tid + i * NT];
            v[4*i+0] = f.x; v[4*i+1] = f.y; v[4*i+2] = f.z; v[4*i+3] = f.w;
        }
    }
    __syncthreads();                       // hist zeros visible

    // Refinement window: bit range [lo, lo+rng), bins of width 2^shift.
    // above = count(bits >= lo+rng). Invariants: above < K.
    uint32_t lo    = 1u;                   // smallest positive bit pattern
    uint32_t rng   = 0x80000000u;          // covers all positive floats
    int      shift = 21;                   // 2^31 / 2^21 = 1024 bins
    uint32_t above = 0u;
    uint32_t Tb = 1u, quota = 0u;
    int tie_path = 0;

    for (;;) {
        // ---- histogram with warp-aggregated atomics ----
#pragma unroll
        for (int j = 0; j < NPT; j++) {
            uint32_t d = __float_as_uint(v[j]) - lo;   // wraps if bits < lo
            bool ok = (v[j] > 0.0f) && (d < rng);
            uint32_t b = ok ? (d >> shift) : 0xFFFFFFFFu;
            uint32_t m = __match_any_sync(0xFFFFFFFFu, b);
            if (ok && lane == (int)(__ffs(m) - 1))
                atomicAdd(&s_hist[b], (uint32_t)__popc(m));
        }
        __syncthreads();                   // B1: histogram complete

        // ---- suffix scan; re-zero hist and clear found-flag for reuse ----
        const int rb = NBIN - 1 - tid;     // bin owned by this thread
        const uint32_t h = s_hist[rb];
        s_hist[rb] = 0u;
        if (tid == 0) s_bc[3] = 0u;
        uint32_t incl = h;
#pragma unroll
        for (int o = 1; o < 32; o <<= 1) {
            uint32_t u = __shfl_up_sync(0xFFFFFFFFu, incl, o);
            if (lane >= o) incl += u;
        }
        if (lane == 31) s_w[wid] = incl;
        __syncthreads();                   // B2: warp totals ready

        if (wid == 0) {                    // exclusive scan of 32 warp totals
            uint32_t t = s_w[lane];
            uint32_t e = t;
#pragma unroll
            for (int o = 1; o < 32; o <<= 1) {
                uint32_t u = __shfl_up_sync(0xFFFFFFFFu, e, o);
                if (lane >= o) e += u;
            }
            s_w[lane] = e - t;
        }
        __syncthreads();                   // B3: warp bases ready

        const uint32_t suf = incl + s_w[wid];   // #elems in bins >= rb
        if (suf + above >= KSEL && (suf - h) + above < KSEL) {  // unique crossing
            s_bc[0] = (uint32_t)rb;
            s_bc[1] = above + (suf - h);   // count(bits >= bin end)
            s_bc[2] = h;                   // crossing-bin population
            s_bc[3] = 1u;
        }
        __syncthreads();                   // B4: crossing published

        if (s_bc[3] == 0u) {               // <K positives: output = relu(x)
            Tb = 1u; tie_path = 0; break;
        }
        const uint32_t bstar = s_bc[0];
        above = s_bc[1];
        const uint32_t hb = s_bc[2];
        const uint32_t r  = KSEL - above;  // rank within bin, 1 <= r <= hb
        lo += bstar << shift;
        if (r == hb) {                     // whole bin kept => exactly K
            Tb = lo; tie_path = 0; break;
        }
        if (shift == 0) {                  // width-1 bin: exact value, dup ties
            Tb = lo; quota = r; tie_path = 1; break;
        }
        rng = 1u << shift;
        shift = (shift >= 10) ? (shift - 10) : 0;
    }

    float4* __restrict__ ov = reinterpret_cast<float4*>(out + base);
    const float T = __uint_as_float(Tb);

    if (!tie_path) {
        // common case: keep everything >= T; T > 0 implements relu for the rest
#pragma unroll
        for (int i = 0; i < 2; i++) {
            float4 o;
            o.x = (v[4*i+0] >= T) ? v[4*i+0] : 0.0f;
            o.y = (v[4*i+1] >= T) ? v[4*i+1] : 0.0f;
            o.z = (v[4*i+2] >= T) ? v[4*i+2] : 0.0f;
            o.w = (v[4*i+3] >= T) ? v[4*i+3] : 0.0f;
            ov[tid + i * NT] = o;
        }
    } else {
        // rare: bit-identical duplicates straddle rank K. Keep the `quota`
        // LOWEST-INDEX ties (jax.lax.top_k tie rule), fully deterministic.
        // Column order is (i, tid, e); rank ties via packed block scan.
        uint32_t tc0 = 0, tc1 = 0;
        bool tie[NPT];
#pragma unroll
        for (int e = 0; e < 4; e++) { tie[e]   = (v[e]   == T); tc0 += tie[e]   ? 1u : 0u; }
#pragma unroll
        for (int e = 0; e < 4; e++) { tie[4+e] = (v[4+e] == T); tc1 += tie[4+e] ? 1u : 0u; }
        uint32_t packed = tc0 | (tc1 << 16);

        uint32_t incl = packed;
#pragma unroll
        for (int o = 1; o < 32; o <<= 1) {
            uint32_t u = __shfl_up_sync(0xFFFFFFFFu, incl, o);
            if (lane >= o) incl += u;
        }
        if (lane == 31) s_w[wid] = incl;
        __syncthreads();
        if (wid == 0) {
            uint32_t t = s_w[lane];
            uint32_t e = t;
#pragma unroll
            for (int o = 1; o < 32; o <<= 1) {
                uint32_t u = __shfl_up_sync(0xFFFFFFFFu, e, o);
                if (lane >= o) e += u;
            }
            s_w[lane] = e - t;             // exclusive warp base
            if (lane == 31) s_bc[0] = e;   // block total (packed)
        }
        __syncthreads();
        const uint32_t excl = s_w[wid] + incl - packed;
        const uint32_t total0 = s_bc[0] & 0xFFFFu;   // ties in i=0 half

        uint32_t rank0 = excl & 0xFFFFu;             // ties before me, i=0 half
        uint32_t rank1 = total0 + (excl >> 16);      // ties before me, i=1 half

        float4 o0, o1; float a;
        a = v[0]; o0.x = (a > T) ? a : ((tie[0] && rank0++ < quota) ? a : 0.0f);
        a = v[1]; o0.y = (a > T) ? a : ((tie[1] && rank0++ < quota) ? a : 0.0f);
        a = v[2]; o0.z = (a > T) ? a : ((tie[2] && rank0++ < quota) ? a : 0.0f);
        a = v[3]; o0.w = (a > T) ? a : ((tie[3] && rank0++ < quota) ? a : 0.0f);
        a = v[4]; o1.x = (a > T) ? a : ((tie[4] && rank1++ < quota) ? a : 0.0f);
        a = v[5]; o1.y = (a > T) ? a : ((tie[5] && rank1++ < quota) ? a : 0.0f);
        a = v[6]; o1.z = (a > T) ? a : ((tie[6] && rank1++ < quota) ? a : 0.0f);
        a = v[7]; o1.w = (a > T) ? a : ((tie[7] && rank1++ < quota) ? a : 0.0f);
        ov[tid]      = o0;
        ov[tid + NT] = o1;
    }
}

extern "C" void kernel_launch(void* const* d_in, const int* in_sizes, int n_in,
                              void* d_out, int out_size) {
    const float* x = (const float*)d_in[0];
    float* out = (float*)d_out;
    int rows = in_sizes[0] / ROWLEN;
    topk_relu_kernel<<<rows, NT>>>(x, out);
}

// round 7
// speedup vs baseline: 2.6562x; 2.6562x over previous
#include <cuda_runtime.h>
#include <stdint.h>

#define ROWLEN 8192
#define NT     1024
#define NPT    8              // ROWLEN / NT
#define NWARP  32
#define KSEL   128
#define NBIN   1024
#define T0BITS 0x3FF00000u   // 1.875f: count(x>=t0) ~ 249 +/- 16 per N(0,1) row
#define SHIFT1 11            // primary bins: width 2^11 ulps, cover up to 9.06

// Per-row top-K of relu(x): keep K largest positive values, zero the rest.
// One fine histogram pass over the ~250 elements >= t0 resolves the K-th
// value threshold almost always; a uniform refinement loop handles the rest.
// Threshold ties are broken by LOWEST COLUMN INDEX (jax.lax.top_k rule) via a
// deterministic block scan -> bit-identical output on every call.
__global__ __launch_bounds__(NT, 2)
void topk_relu_kernel(const float* __restrict__ x, float* __restrict__ out) {
    __shared__ uint32_t s_hist[NBIN];
    __shared__ uint32_t s_w[NWARP];
    __shared__ uint32_t s_bc[5];   // 0=bstar 1=above_new 2=h 3=found 4=window total

    const int tid  = threadIdx.x;
    const int wid  = tid >> 5;
    const int lane = tid & 31;
    const size_t base = (size_t)blockIdx.x * ROWLEN;

    s_hist[tid] = 0u;

    // ---- single HBM read: row -> registers ----
    // v[4*i+e] holds column 4*(i*NT + tid) + e  => column order = (i, tid, e)
    float v[NPT];
    {
        const float4* __restrict__ xv = reinterpret_cast<const float4*>(x + base);
#pragma unroll
        for (int i = 0; i < 2; i++) {
            float4 f = xv[tid + i * NT];
            v[4*i+0] = f.x; v[4*i+1] = f.y; v[4*i+2] = f.z; v[4*i+3] = f.w;
        }
    }
    __syncthreads();                        // hist zeros visible

    // Window state: bit range [lo, lo+rng), bins width 2^shift, top-clamped
    // when `clamped` (bin NBIN-1 absorbs everything above). `above` = count of
    // elements with bits >= window end. Invariant: above < K.
    uint32_t lo    = T0BITS;
    uint32_t rng   = 0xFFFFFFFFu;           // clamped window: no upper bound
    int      shift = SHIFT1;
    uint32_t above = 0u;
    bool clamped = true, first = true;
    uint32_t Tb = 1u, quota = 0u;
    int tie_path = 0;

    for (;;) {
        // ---- histogram of in-window elements (plain atomics, sparse bins) ----
        const float lof = __uint_as_float(lo);
#pragma unroll
        for (int j = 0; j < NPT; j++) {
            if (v[j] >= lof) {              // positive & bits >= lo
                uint32_t d = __float_as_uint(v[j]) - lo;
                if (d < rng) {
                    uint32_t b = d >> shift;
                    if (b > NBIN - 1u) b = NBIN - 1u;   // clamp (clamped windows)
                    atomicAdd(&s_hist[b], 1u);
                }
            }
        }
        __syncthreads();                    // B1: histogram complete

        // ---- suffix scan; re-zero hist; clear found-flag ----
        const int rb = NBIN - 1 - tid;
        const uint32_t h = s_hist[rb];
        s_hist[rb] = 0u;
        if (tid == 0) s_bc[3] = 0u;
        uint32_t incl = h;
#pragma unroll
        for (int o = 1; o < 32; o <<= 1) {
            uint32_t u = __shfl_up_sync(0xFFFFFFFFu, incl, o);
            if (lane >= o) incl += u;
        }
        if (lane == 31) s_w[wid] = incl;
        __syncthreads();                    // B2: warp totals ready

        if (wid == 0) {                     // exclusive scan of 32 warp totals
            uint32_t t = s_w[lane];
            uint32_t e = t;
#pragma unroll
            for (int o = 1; o < 32; o <<= 1) {
                uint32_t u = __shfl_up_sync(0xFFFFFFFFu, e, o);
                if (lane >= o) e += u;
            }
            s_w[lane] = e - t;
        }
        __syncthreads();                    // B3: warp bases ready

        const uint32_t suf = incl + s_w[wid];          // #elems in bins >= rb
        if (suf + above >= KSEL && (suf - h) + above < KSEL) {   // unique crossing
            s_bc[0] = (uint32_t)rb;
            s_bc[1] = above + (suf - h);    // count(bits >= crossing-bin end)
            s_bc[2] = h;
        }
        if (suf + above >= KSEL && (suf - h) + above < KSEL) s_bc[3] = 1u;
        if (rb == 0) s_bc[4] = suf;         // window total
        __syncthreads();                    // B4: crossing published

        if (s_bc[3] == 0u) {
            if (first) {
                // count(>= t0) < K: search the remaining range (0, t0)
                above = s_bc[4];
                lo = 1u; rng = T0BITS - 1u; shift = 20;
                clamped = false; first = false;
                continue;
            }
            Tb = 1u; tie_path = 0; break;   // <K positives: output = relu(x)
        }
        first = false;
        const uint32_t bstar = s_bc[0];
        above = s_bc[1];
        const uint32_t hb = s_bc[2];
        const uint32_t r  = KSEL - above;   // rank within bin, 1 <= r <= hb
        lo += bstar << shift;               // crossing-bin start
        if (r == hb) {                      // keep whole bin => exactly K
            Tb = lo; tie_path = 0; break;
        }
        if (shift == 0) {                   // width-1 bin: exact value, dup ties
            Tb = lo; quota = r; tie_path = 1; break;
        }
        if (clamped && bstar == NBIN - 1u) {
            // refining the clamp bin: reopen to [lo, +inf) at coarse bins
            rng = 0xFFFFFFFFu; shift = 20; clamped = false;
        } else {
            rng = 1u << shift;
            shift = (shift > 10) ? (shift - 10) : 0;
            clamped = false;
        }
    }

    // ---- output straight from registers (single HBM write) ----
    float4* __restrict__ ov = reinterpret_cast<float4*>(out + base);
    const float T = __uint_as_float(Tb);

    if (!tie_path) {
        // common case: keep everything >= T; T > 0 implements relu for the rest
#pragma unroll
        for (int i = 0; i < 2; i++) {
            float4 o;
            o.x = (v[4*i+0] >= T) ? v[4*i+0] : 0.0f;
            o.y = (v[4*i+1] >= T) ? v[4*i+1] : 0.0f;
            o.z = (v[4*i+2] >= T) ? v[4*i+2] : 0.0f;
            o.w = (v[4*i+3] >= T) ? v[4*i+3] : 0.0f;
            ov[tid + i * NT] = o;
        }
    } else {
        // rare: bit-identical duplicates straddle rank K. Keep the `quota`
        // LOWEST-INDEX ties, deterministically, via packed block scan.
        uint32_t tc0 = 0, tc1 = 0;
        bool tie[NPT];
#pragma unroll
        for (int e = 0; e < 4; e++) { tie[e]   = (v[e]   == T); tc0 += tie[e]   ? 1u : 0u; }
#pragma unroll
        for (int e = 0; e < 4; e++) { tie[4+e] = (v[4+e] == T); tc1 += tie[4+e] ? 1u : 0u; }
        uint32_t packed = tc0 | (tc1 << 16);

        uint32_t incl = packed;
#pragma unroll
        for (int o = 1; o < 32; o <<= 1) {
            uint32_t u = __shfl_up_sync(0xFFFFFFFFu, incl, o);
            if (lane >= o) incl += u;
        }
        if (lane == 31) s_w[wid] = incl;
        __syncthreads();
        if (wid == 0) {
            uint32_t t = s_w[lane];
            uint32_t e = t;
#pragma unroll
            for (int o = 1; o < 32; o <<= 1) {
                uint32_t u = __shfl_up_sync(0xFFFFFFFFu, e, o);
                if (lane >= o) e += u;
            }
            s_w[lane] = e - t;              // exclusive warp base
            if (lane == 31) s_bc[0] = e;    // block total (packed)
        }
        __syncthreads();
        const uint32_t excl = s_w[wid] + incl - packed;
        const uint32_t total0 = s_bc[0] & 0xFFFFu;     // ties in i=0 half

        uint32_t rank0 = excl & 0xFFFFu;               // ties before me, i=0 half
        uint32_t rank1 = total0 + (excl >> 16);        // ties before me, i=1 half

        float4 o0, o1; float a;
        a = v[0]; o0.x = (a > T) ? a : ((tie[0] && rank0++ < quota) ? a : 0.0f);
        a = v[1]; o0.y = (a > T) ? a : ((tie[1] && rank0++ < quota) ? a : 0.0f);
        a = v[2]; o0.z = (a > T) ? a : ((tie[2] && rank0++ < quota) ? a : 0.0f);
        a = v[3]; o0.w = (a > T) ? a : ((tie[3] && rank0++ < quota) ? a : 0.0f);
        a = v[4]; o1.x = (a > T) ? a : ((tie[4] && rank1++ < quota) ? a : 0.0f);
        a = v[5]; o1.y = (a > T) ? a : ((tie[5] && rank1++ < quota) ? a : 0.0f);
        a = v[6]; o1.z = (a > T) ? a : ((tie[6] && rank1++ < quota) ? a : 0.0f);
        a = v[7]; o1.w = (a > T) ? a : ((tie[7] && rank1++ < quota) ? a : 0.0f);
        ov[tid]      = o0;
        ov[tid + NT] = o1;
    }
}

extern "C" void kernel_launch(void* const* d_in, const int* in_sizes, int n_in,
                              void* d_out, int out_size) {
    const float* x = (const float*)d_in[0];
    float* out = (float*)d_out;
    int rows = in_sizes[0] / ROWLEN;
    topk_relu_kernel<<<rows, NT>>>(x, out);
}

// round 8
// speedup vs baseline: 2.7037x; 1.0179x over previous
#include <cuda_runtime.h>
#include <stdint.h>

#define ROWLEN   8192
#define NT       1024
#define NPT      8              // ROWLEN / NT
#define NWARP    32
#define KSEL     128
#define NBIN     1024
#define T0BITS   0x3FF00000u    // 1.875f: count(x>=t0) ~ 249 +/- 16 per N(0,1) row
#define SHIFT1   11             // primary bins: width 2^11 ulps
#define ROWBYTES (ROWLEN * 4)
#define GRID     304            // persistent CTAs (2 per SM)

__device__ __forceinline__ uint32_t smem_u32(const void* p) {
    uint32_t a;
    asm("{ .reg .u64 t; cvta.to.shared.u64 t, %1; cvt.u32.u64 %0, t; }"
        : "=r"(a) : "l"(p));
    return a;
}

__device__ __forceinline__ void mbar_init(uint32_t m, uint32_t c) {
    asm volatile("mbarrier.init.shared.b64 [%0], %1;" :: "r"(m), "r"(c) : "memory");
}
__device__ __forceinline__ void mbar_expect_tx(uint32_t m, uint32_t bytes) {
    asm volatile("mbarrier.arrive.expect_tx.shared.b64 _, [%0], %1;"
                 :: "r"(m), "r"(bytes) : "memory");
}
__device__ __forceinline__ void bulk_g2s(uint32_t dst, const void* src,
                                         uint32_t bytes, uint32_t m) {
    asm volatile("cp.async.bulk.shared::cluster.global.mbarrier::complete_tx::bytes "
                 "[%0], [%1], %2, [%3];"
                 :: "r"(dst), "l"(src), "r"(bytes), "r"(m) : "memory");
}
__device__ __forceinline__ void mbar_wait(uint32_t m, uint32_t ph) {
    uint32_t done;
    do {
        asm volatile("{ .reg .pred p; "
                     "mbarrier.try_wait.parity.acquire.cta.shared::cta.b64 p, [%1], %2; "
                     "selp.b32 %0, 1, 0, p; }"
                     : "=r"(done) : "r"(m), "r"(ph) : "memory");
    } while (!done);
}

struct SMem {
    float4   row[ROWLEN / 4];       // 32 KB staged row (written only by bulk copy)
    uint32_t hist[NBIN];            // 4 KB
    uint32_t w[NWARP];
    uint32_t bc[5];                 // 0=bstar 1=above_new 2=h 3=found 4=window total
    unsigned long long mbar;
};

// Persistent per-row top-K of relu(x). Row r+1 streams HBM->SMEM via
// cp.async.bulk while row r's selection runs -> DRAM stays busy through the
// barrier-heavy phases. Selection = pre-filtered (t0=1.875) 1024-bin histogram
// refinement in positive-float bit space; ties at the threshold broken by
// LOWEST COLUMN INDEX (jax.lax.top_k rule) via a deterministic block scan.
__global__ __launch_bounds__(NT, 2)
void topk_relu_kernel(const float* __restrict__ x, float* __restrict__ out,
                      int rows) {
    __shared__ SMem sm;
    const int tid  = threadIdx.x;
    const int wid  = tid >> 5;
    const int lane = tid & 31;

    const uint32_t mb   = smem_u32(&sm.mbar);
    const uint32_t rowa = smem_u32(&sm.row[0]);

    sm.hist[tid] = 0u;
    if (tid == 0) mbar_init(mb, 1u);
    __syncthreads();

    int r = blockIdx.x;
    if (tid == 0 && r < rows)  // prologue prefetch
        { mbar_expect_tx(mb, ROWBYTES); bulk_g2s(rowa, x + (size_t)r * ROWLEN, ROWBYTES, mb); }
    uint32_t phase = 0;

    for (; r < rows; r += GRID) {
        mbar_wait(mb, phase); phase ^= 1;      // row r resident in smem

        // ---- smem -> registers; column order = (i, tid, e) ----
        float v[NPT];
        {
            float4 f0 = sm.row[tid];
            float4 f1 = sm.row[tid + NT];
            v[0] = f0.x; v[1] = f0.y; v[2] = f0.z; v[3] = f0.w;
            v[4] = f1.x; v[5] = f1.y; v[6] = f1.z; v[7] = f1.w;
        }
        __syncthreads();                       // all copied -> buffer reusable

        if (tid == 0) {                        // prefetch row r+GRID
            int rn = r + GRID;
            if (rn < rows) {
                mbar_expect_tx(mb, ROWBYTES);
                bulk_g2s(rowa, x + (size_t)rn * ROWLEN, ROWBYTES, mb);
            }
        }

        // ==== selection: histogram refinement (bit space of positive floats) ====
        uint32_t lo = T0BITS, rng = 0xFFFFFFFFu;
        int shift = SHIFT1;
        uint32_t above = 0u;
        bool clamped = true, first = true;
        uint32_t Tb = 1u, quota = 0u;
        int tie_path = 0;

        for (;;) {
            const float lof = __uint_as_float(lo);
#pragma unroll
            for (int j = 0; j < NPT; j++) {
                if (v[j] >= lof) {             // positive & bits >= lo
                    uint32_t d = __float_as_uint(v[j]) - lo;
                    if (d < rng) {
                        uint32_t b = d >> shift;
                        if (b > NBIN - 1u) b = NBIN - 1u;
                        atomicAdd(&sm.hist[b], 1u);
                    }
                }
            }
            __syncthreads();                   // B1: histogram complete

            const int rb = NBIN - 1 - tid;
            const uint32_t h = sm.hist[rb];
            sm.hist[rb] = 0u;                  // re-zero for next use
            if (tid == 0) sm.bc[3] = 0u;
            uint32_t incl = h;
#pragma unroll
            for (int o = 1; o < 32; o <<= 1) {
                uint32_t u = __shfl_up_sync(0xFFFFFFFFu, incl, o);
                if (lane >= o) incl += u;
            }
            if (lane == 31) sm.w[wid] = incl;
            __syncthreads();                   // B2: warp totals ready

            // redundant per-warp scan of the 32 warp totals (no extra barrier)
            uint32_t t = sm.w[lane];
            uint32_t sc = t;
#pragma unroll
            for (int o = 1; o < 32; o <<= 1) {
                uint32_t u = __shfl_up_sync(0xFFFFFFFFu, sc, o);
                if (lane >= o) sc += u;
            }
            uint32_t basew = (wid == 0) ? 0u
                             : __shfl_sync(0xFFFFFFFFu, sc, wid - 1);
            const uint32_t suf = incl + basew; // #elems in bins >= rb
            if (suf + above >= KSEL && (suf - h) + above < KSEL) { // unique crossing
                sm.bc[0] = (uint32_t)rb;
                sm.bc[1] = above + (suf - h);
                sm.bc[2] = h;
                sm.bc[3] = 1u;
            }
            if (rb == 0) sm.bc[4] = suf;       // window total
            __syncthreads();                   // B3: crossing published

            if (sm.bc[3] == 0u) {
                if (first) {                   // count(>= t0) < K: search (0, t0)
                    above = sm.bc[4];
                    lo = 1u; rng = T0BITS - 1u; shift = 20;
                    clamped = false; first = false;
                    continue;
                }
                Tb = 1u; tie_path = 0; break;  // <K positives: output = relu(x)
            }
            first = false;
            const uint32_t bstar = sm.bc[0];
            above = sm.bc[1];
            const uint32_t hb = sm.bc[2];
            const uint32_t rk = KSEL - above;  // rank within bin, 1 <= rk <= hb
            lo += bstar << shift;
            if (rk == hb) { Tb = lo; tie_path = 0; break; }   // whole bin => K
            if (shift == 0) { Tb = lo; quota = rk; tie_path = 1; break; }
            if (clamped && bstar == NBIN - 1u) {
                rng = 0xFFFFFFFFu; shift = 20; clamped = false;  // reopen clamp bin
            } else {
                rng = 1u << shift;
                shift = (shift > 10) ? (shift - 10) : 0;
                clamped = false;
            }
        }

        // ==== output straight from registers ====
        float4* __restrict__ ov = reinterpret_cast<float4*>(out + (size_t)r * ROWLEN);
        const float T = __uint_as_float(Tb);

        if (!tie_path) {
            float4 o0, o1;
            o0.x = (v[0] >= T) ? v[0] : 0.0f;
            o0.y = (v[1] >= T) ? v[1] : 0.0f;
            o0.z = (v[2] >= T) ? v[2] : 0.0f;
            o0.w = (v[3] >= T) ? v[3] : 0.0f;
            o1.x = (v[4] >= T) ? v[4] : 0.0f;
            o1.y = (v[5] >= T) ? v[5] : 0.0f;
            o1.z = (v[6] >= T) ? v[6] : 0.0f;
            o1.w = (v[7] >= T) ? v[7] : 0.0f;
            ov[tid]      = o0;
            ov[tid + NT] = o1;
        } else {
            // duplicates straddle rank K: keep `quota` lowest-index ties.
            uint32_t tc0 = 0, tc1 = 0;
            bool tie[NPT];
#pragma unroll
            for (int e = 0; e < 4; e++) { tie[e]   = (v[e]   == T); tc0 += tie[e]   ? 1u : 0u; }
#pragma unroll
            for (int e = 0; e < 4; e++) { tie[4+e] = (v[4+e] == T); tc1 += tie[4+e] ? 1u : 0u; }
            uint32_t packed = tc0 | (tc1 << 16);

            uint32_t incl = packed;
#pragma unroll
            for (int o = 1; o < 32; o <<= 1) {
                uint32_t u = __shfl_up_sync(0xFFFFFFFFu, incl, o);
                if (lane >= o) incl += u;
            }
            if (lane == 31) sm.w[wid] = incl;
            __syncthreads();
            uint32_t t2 = sm.w[lane];
            uint32_t sc2 = t2;
#pragma unroll
            for (int o = 1; o < 32; o <<= 1) {
                uint32_t u = __shfl_up_sync(0xFFFFFFFFu, sc2, o);
                if (lane >= o) sc2 += u;
            }
            uint32_t basew = (wid == 0) ? 0u
                             : __shfl_sync(0xFFFFFFFFu, sc2, wid - 1);
            uint32_t total0 = __shfl_sync(0xFFFFFFFFu, sc2, 31) & 0xFFFFu;
            const uint32_t excl = basew + incl - packed;

            uint32_t rank0 = excl & 0xFFFFu;
            uint32_t rank1 = total0 + (excl >> 16);

            float4 o0, o1; float a;
            a = v[0]; o0.x = (a > T) ? a : ((tie[0] && rank0++ < quota) ? a : 0.0f);
            a = v[1]; o0.y = (a > T) ? a : ((tie[1] && rank0++ < quota) ? a : 0.0f);
            a = v[2]; o0.z = (a > T) ? a : ((tie[2] && rank0++ < quota) ? a : 0.0f);
            a = v[3]; o0.w = (a > T) ? a : ((tie[3] && rank0++ < quota) ? a : 0.0f);
            a = v[4]; o1.x = (a > T) ? a : ((tie[4] && rank1++ < quota) ? a : 0.0f);
            a = v[5]; o1.y = (a > T) ? a : ((tie[5] && rank1++ < quota) ? a : 0.0f);
            a = v[6]; o1.z = (a > T) ? a : ((tie[6] && rank1++ < quota) ? a : 0.0f);
            a = v[7]; o1.w = (a > T) ? a : ((tie[7] && rank1++ < quota) ? a : 0.0f);
            ov[tid]      = o0;
            ov[tid + NT] = o1;
            __syncthreads();                   // protect sm.w before next row's reuse
        }
    }
}

extern "C" void kernel_launch(void* const* d_in, const int* in_sizes, int n_in,
                              void* d_out, int out_size) {
    const float* x = (const float*)d_in[0];
    float* out = (float*)d_out;
    int rows = in_sizes[0] / ROWLEN;
    int grid = (rows < GRID) ? rows : GRID;
    topk_relu_kernel<<<grid, NT>>>(x, out, rows);
}